// round 1
// baseline (speedup 1.0000x reference)
#include <cuda_runtime.h>
#include <math.h>

#define SQ   2048
#define HID  768
#define NH   12
#define HD   64
#define NF   128
#define KE   192   // HD + NF extended contraction dim

// ---------------- scratch (allocation-free: device globals) ----------------
__device__ float g_Qext[NH * SQ * KE];        // [h][s][0:64]=0.1125*q, [64:192]=0.1*phi_q
__device__ float g_Kext[NH * SQ * KE];        // [h][s][0:64]=k,        [64:192]=phi_k
__device__ float g_V   [NH * SQ * HD];
__device__ float g_Ctx [SQ * HID];
__device__ float g_Wsc [ (size_t)NH * SQ * SQ ]; // fallback weights buffer

// =======================================================================
// Shared ABt tile engine: C[i][j] = sum_k A[i][k]*B[j][k]
// BM=BN=128, BK=16, 256 threads, 8x8 microtile.
// =======================================================================
__device__ __forceinline__ void abt_body(const float* __restrict__ A,
                                         const float* __restrict__ B,
                                         int K, int lda, int ldb,
                                         float (*As)[132], float (*Bs)[132],
                                         float acc[8][8])
{
    const int tid = threadIdx.x;
    const int lr = tid >> 2;           // 0..63
    const int lc = (tid & 3) << 2;     // 0,4,8,12
    const int tx = tid & 15;
    const int ty = tid >> 4;

    for (int k0 = 0; k0 < K; k0 += 16) {
        float4 a0 = *(const float4*)(A + (size_t)(lr      ) * lda + k0 + lc);
        float4 a1 = *(const float4*)(A + (size_t)(lr +  64) * lda + k0 + lc);
        float4 b0 = *(const float4*)(B + (size_t)(lr      ) * ldb + k0 + lc);
        float4 b1 = *(const float4*)(B + (size_t)(lr +  64) * ldb + k0 + lc);
        __syncthreads();
        As[lc+0][lr] = a0.x; As[lc+1][lr] = a0.y; As[lc+2][lr] = a0.z; As[lc+3][lr] = a0.w;
        As[lc+0][lr+64] = a1.x; As[lc+1][lr+64] = a1.y; As[lc+2][lr+64] = a1.z; As[lc+3][lr+64] = a1.w;
        Bs[lc+0][lr] = b0.x; Bs[lc+1][lr] = b0.y; Bs[lc+2][lr] = b0.z; Bs[lc+3][lr] = b0.w;
        Bs[lc+0][lr+64] = b1.x; Bs[lc+1][lr+64] = b1.y; Bs[lc+2][lr+64] = b1.z; Bs[lc+3][lr+64] = b1.w;
        __syncthreads();
#pragma unroll
        for (int k = 0; k < 16; k++) {
            float4 av0 = *(const float4*)&As[k][ty * 8];
            float4 av1 = *(const float4*)&As[k][ty * 8 + 4];
            float4 bv0 = *(const float4*)&Bs[k][tx * 8];
            float4 bv1 = *(const float4*)&Bs[k][tx * 8 + 4];
            float a[8] = {av0.x, av0.y, av0.z, av0.w, av1.x, av1.y, av1.z, av1.w};
            float b[8] = {bv0.x, bv0.y, bv0.z, bv0.w, bv1.x, bv1.y, bv1.z, bv1.w};
#pragma unroll
            for (int i = 0; i < 8; i++)
#pragma unroll
                for (int j = 0; j < 8; j++)
                    acc[i][j] += a[i] * b[j];
        }
    }
}

// =======================================================================
// K1: QKV projections. z = 0:Q 1:K 2:V. C = X @ W^T + b, scatter to head layout.
// grid (HID/128=6, SQ/128=16, 3), 256 thr
// =======================================================================
__global__ __launch_bounds__(256) void k_qkv(const float* __restrict__ X,
    const float* __restrict__ Wq, const float* __restrict__ bq,
    const float* __restrict__ Wk, const float* __restrict__ bk,
    const float* __restrict__ Wv, const float* __restrict__ bv)
{
    __shared__ float As[16][132];
    __shared__ float Bs[16][132];
    const int z = blockIdx.z;
    const float* W    = (z == 0) ? Wq : (z == 1) ? Wk : Wv;
    const float* bias = (z == 0) ? bq : (z == 1) ? bk : bv;
    const int rowBase = blockIdx.y * 128;
    const int colBase = blockIdx.x * 128;

    float acc[8][8];
#pragma unroll
    for (int i = 0; i < 8; i++)
#pragma unroll
        for (int j = 0; j < 8; j++) acc[i][j] = 0.f;

    abt_body(X + (size_t)rowBase * HID, W + (size_t)colBase * HID,
             HID, HID, HID, As, Bs, acc);

    const int tx = threadIdx.x & 15, ty = threadIdx.x >> 4;
#pragma unroll
    for (int i = 0; i < 8; i++) {
        const int s = rowBase + ty * 8 + i;
#pragma unroll
        for (int j = 0; j < 8; j++) {
            const int o = colBase + tx * 8 + j;
            const float c = acc[i][j] + bias[o];
            const int h = o >> 6, d = o & 63;
            if (z == 2)       g_V[((size_t)h * SQ + s) * HD + d] = c;
            else if (z == 1)  g_Kext[((size_t)h * SQ + s) * KE + d] = c;
            else              g_Qext[((size_t)h * SQ + s) * KE + d] = c;
        }
    }
}

// =======================================================================
// K2: RFF features. grid (SQ/64=32, NH, 2: side 0=Q 1=K), 128 thr (thread = feature f)
// =======================================================================
__device__ __forceinline__ float blockReduceSum128(float v, volatile float* red)
{
    for (int o = 16; o > 0; o >>= 1) v += __shfl_xor_sync(0xffffffffu, v, o);
    const int w = threadIdx.x >> 5;
    if ((threadIdx.x & 31) == 0) red[w] = v;
    __syncthreads();
    return red[0] + red[1] + red[2] + red[3];
}

#define OMLD 129

__global__ __launch_bounds__(128) void k_phi(const float* __restrict__ omega,
                                             const float* __restrict__ rffb)
{
    __shared__ float omT[HD * OMLD];   // [d][f] padded, conflict-free both ways
    __shared__ float qrow[HD];
    __shared__ float redA[4];
    __shared__ float redB[4];

    const int tid  = threadIdx.x;
    const int h    = blockIdx.y;
    const int side = blockIdx.z;       // 0 -> Q, 1 -> K

    // load omega[h] transposed: read coalesced, store conflict-free (pad 129)
    for (int i = tid; i < NF * HD; i += 128) {
        const int f = i >> 6, d = i & 63;
        omT[d * OMLD + f] = omega[((size_t)h * NF + f) * HD + d];
    }
    const float bf = rffb[h * NF + tid];
    float* ext = (side ? g_Kext : g_Qext) + (size_t)h * SQ * KE;
    const float segscale = side ? 1.0f : 0.1f;      // (1-ALPHA) on Q side
    __syncthreads();

    for (int r = 0; r < 64; r++) {
        const int s = blockIdx.x * 64 + r;
        float* row = ext + (size_t)s * KE;
        __syncthreads();                  // protects qrow/red reuse across rows
        if (tid < 64) qrow[tid] = row[tid];
        __syncthreads();

        float p = (tid < 64) ? qrow[tid] * qrow[tid] : 0.f;
        const float ss  = blockReduceSum128(p, redA);
        const float inv = 1.0f / (sqrtf(ss) + 1e-5f);

        float dot = 0.f;
#pragma unroll 8
        for (int d = 0; d < HD; d++) dot += qrow[d] * omT[d * OMLD + tid];
        const float zv = inv * dot + bf;
        const float ph = 0.125f * cosf(zv);   // sqrt(2/NF)=0.125

        __syncthreads();                  // redA reads done before redB store pattern overlap
        const float pn2 = blockReduceSum128(ph * ph, redB);
        const float outv = ph / (sqrtf(pn2) + 1e-6f);

        row[HD + tid] = outv * segscale;
        if (side == 0 && tid < 64) row[tid] = qrow[tid] * 0.1125f;  // ALPHA/sqrt(HD)
    }
}

// =======================================================================
// K3: scores = Qext @ Kext^T + maskadd. grid (16,16,NH), 256 thr
// =======================================================================
__global__ __launch_bounds__(256) void k_scores(const float* __restrict__ mask,
                                                float* wts)
{
    __shared__ float As[16][132];
    __shared__ float Bs[16][132];
    float* W = wts ? wts : g_Wsc;
    const int h = blockIdx.z;
    const int rowBase = blockIdx.y * 128;
    const int colBase = blockIdx.x * 128;

    float acc[8][8];
#pragma unroll
    for (int i = 0; i < 8; i++)
#pragma unroll
        for (int j = 0; j < 8; j++) acc[i][j] = 0.f;

    const float* A = g_Qext + (size_t)h * SQ * KE + (size_t)rowBase * KE;
    const float* B = g_Kext + (size_t)h * SQ * KE + (size_t)colBase * KE;
    abt_body(A, B, KE, KE, KE, As, Bs, acc);

    float* Wh = W + (size_t)h * SQ * SQ;
    const int tx = threadIdx.x & 15, ty = threadIdx.x >> 4;
#pragma unroll
    for (int i = 0; i < 8; i++) {
        const int s = rowBase + ty * 8 + i;
#pragma unroll
        for (int j = 0; j < 8; j++) {
            const int t = colBase + tx * 8 + j;
            Wh[(size_t)s * SQ + t] = acc[i][j] + (mask[t] - 1.0f) * 10000.0f;
        }
    }
}

// =======================================================================
// K4: in-place row softmax over 2048 cols. grid (NH*SQ), 256 thr
// =======================================================================
__global__ __launch_bounds__(256) void k_softmax(float* wts)
{
    __shared__ float red[8];
    float* W = wts ? wts : g_Wsc;
    float4* p = (float4*)(W + (size_t)blockIdx.x * SQ);
    const int tid = threadIdx.x;

    float4 v0 = p[tid];
    float4 v1 = p[tid + 256];
    float m = fmaxf(fmaxf(fmaxf(v0.x, v0.y), fmaxf(v0.z, v0.w)),
                    fmaxf(fmaxf(v1.x, v1.y), fmaxf(v1.z, v1.w)));
    for (int o = 16; o > 0; o >>= 1) m = fmaxf(m, __shfl_xor_sync(0xffffffffu, m, o));
    if ((tid & 31) == 0) red[tid >> 5] = m;
    __syncthreads();
    m = red[0];
#pragma unroll
    for (int i = 1; i < 8; i++) m = fmaxf(m, red[i]);
    __syncthreads();

    v0.x = expf(v0.x - m); v0.y = expf(v0.y - m); v0.z = expf(v0.z - m); v0.w = expf(v0.w - m);
    v1.x = expf(v1.x - m); v1.y = expf(v1.y - m); v1.z = expf(v1.z - m); v1.w = expf(v1.w - m);
    float s = v0.x + v0.y + v0.z + v0.w + v1.x + v1.y + v1.z + v1.w;
    for (int o = 16; o > 0; o >>= 1) s += __shfl_xor_sync(0xffffffffu, s, o);
    if ((tid & 31) == 0) red[tid >> 5] = s;
    __syncthreads();
    s = red[0] + red[1] + red[2] + red[3] + red[4] + red[5] + red[6] + red[7];
    const float inv = 1.0f / s;

    v0.x *= inv; v0.y *= inv; v0.z *= inv; v0.w *= inv;
    v1.x *= inv; v1.y *= inv; v1.z *= inv; v1.w *= inv;
    p[tid] = v0;
    p[tid + 256] = v1;
}

// =======================================================================
// K5: context = weights @ V. A(2048x2048) row-major * B(2048x64).
// BM=128, BN=64, BK=16. grid (1, 16, NH), 256 thr, 8x4 microtile.
// =======================================================================
__global__ __launch_bounds__(256) void k_context(float* wts)
{
    __shared__ float As[16][132];
    __shared__ float Bs[16][64];
    float* W = wts ? wts : g_Wsc;
    const int h = blockIdx.z;
    const int rowBase = blockIdx.y * 128;
    const float* A = W   + (size_t)h * SQ * SQ + (size_t)rowBase * SQ;
    const float* B = g_V + (size_t)h * SQ * HD;

    const int tid = threadIdx.x;
    const int lr = tid >> 2, lc = (tid & 3) << 2;
    const int br = tid >> 4, bc = (tid & 15) << 2;
    const int tx = tid & 15, ty = tid >> 4;

    float acc[8][4];
#pragma unroll
    for (int i = 0; i < 8; i++)
#pragma unroll
        for (int j = 0; j < 4; j++) acc[i][j] = 0.f;

    for (int k0 = 0; k0 < SQ; k0 += 16) {
        float4 a0 = *(const float4*)(A + (size_t)(lr     ) * SQ + k0 + lc);
        float4 a1 = *(const float4*)(A + (size_t)(lr + 64) * SQ + k0 + lc);
        float4 b0 = *(const float4*)(B + (size_t)(k0 + br) * HD + bc);
        __syncthreads();
        As[lc+0][lr] = a0.x; As[lc+1][lr] = a0.y; As[lc+2][lr] = a0.z; As[lc+3][lr] = a0.w;
        As[lc+0][lr+64] = a1.x; As[lc+1][lr+64] = a1.y; As[lc+2][lr+64] = a1.z; As[lc+3][lr+64] = a1.w;
        *(float4*)&Bs[br][bc] = b0;
        __syncthreads();
#pragma unroll
        for (int k = 0; k < 16; k++) {
            float4 av0 = *(const float4*)&As[k][ty * 8];
            float4 av1 = *(const float4*)&As[k][ty * 8 + 4];
            float4 bv  = *(const float4*)&Bs[k][tx * 4];
            float a[8] = {av0.x, av0.y, av0.z, av0.w, av1.x, av1.y, av1.z, av1.w};
            float b[4] = {bv.x, bv.y, bv.z, bv.w};
#pragma unroll
            for (int i = 0; i < 8; i++)
#pragma unroll
                for (int j = 0; j < 4; j++) acc[i][j] += a[i] * b[j];
        }
    }

#pragma unroll
    for (int i = 0; i < 8; i++) {
        const int s = rowBase + ty * 8 + i;
#pragma unroll
        for (int j = 0; j < 4; j++) {
            const int d = tx * 4 + j;
            g_Ctx[(size_t)s * HID + h * HD + d] = acc[i][j];
        }
    }
}

// =======================================================================
// K6: output = Ctx @ Wo^T + bo. grid (6, 16), 256 thr
// =======================================================================
__global__ __launch_bounds__(256) void k_outproj(const float* __restrict__ Wo,
                                                 const float* __restrict__ bo,
                                                 float* __restrict__ out)
{
    __shared__ float As[16][132];
    __shared__ float Bs[16][132];
    const int rowBase = blockIdx.y * 128;
    const int colBase = blockIdx.x * 128;

    float acc[8][8];
#pragma unroll
    for (int i = 0; i < 8; i++)
#pragma unroll
        for (int j = 0; j < 8; j++) acc[i][j] = 0.f;

    abt_body(g_Ctx + (size_t)rowBase * HID, Wo + (size_t)colBase * HID,
             HID, HID, HID, As, Bs, acc);

    const int tx = threadIdx.x & 15, ty = threadIdx.x >> 4;
#pragma unroll
    for (int i = 0; i < 8; i++) {
        const int s = rowBase + ty * 8 + i;
#pragma unroll
        for (int j = 0; j < 8; j++) {
            const int o = colBase + tx * 8 + j;
            out[(size_t)s * HID + o] = acc[i][j] + bo[o];
        }
    }
}

// =======================================================================
extern "C" void kernel_launch(void* const* d_in, const int* in_sizes, int n_in,
                              void* d_out, int out_size)
{
    const float* X    = (const float*)d_in[0];
    const float* mask = (const float*)d_in[1];
    const float* Wq   = (const float*)d_in[2];
    const float* bq   = (const float*)d_in[3];
    const float* Wk   = (const float*)d_in[4];
    const float* bk   = (const float*)d_in[5];
    const float* Wv   = (const float*)d_in[6];
    const float* bv   = (const float*)d_in[7];
    const float* Wo   = (const float*)d_in[8];
    const float* bo   = (const float*)d_in[9];
    const float* omega = (const float*)d_in[10];
    const float* rffb  = (const float*)d_in[11];

    float* out = (float*)d_out;
    // If harness wants both tuple outputs concatenated (output first, weights second),
    // write weights directly into d_out. Otherwise use device scratch (wts=nullptr).
    float* wts = (out_size > SQ * HID) ? (out + (size_t)SQ * HID) : nullptr;

    k_qkv<<<dim3(HID / 128, SQ / 128, 3), 256>>>(X, Wq, bq, Wk, bk, Wv, bv);
    k_phi<<<dim3(SQ / 64, NH, 2), 128>>>(omega, rffb);
    k_scores<<<dim3(SQ / 128, SQ / 128, NH), 256>>>(mask, wts);
    k_softmax<<<dim3(NH * SQ), 256>>>(wts);
    k_context<<<dim3(1, SQ / 128, NH), 256>>>(wts);
    k_outproj<<<dim3(HID / 128, SQ / 128), 256>>>(Wo, bo, out);
}

// round 2
// speedup vs baseline: 2.0397x; 2.0397x over previous
#include <cuda_runtime.h>
#include <math.h>
#include <stdint.h>

#define SQ   2048
#define HID  768
#define NH   12
#define HD   64
#define NF   128
#define KE   192   // HD + NF extended contraction dim
#define LD   40    // padded smem row (floats): conflict-free fragment reads

// ---------------- scratch (allocation-free: device globals) ----------------
__device__ float g_Qext[NH * SQ * KE];        // [h][s][0:64]=0.1125*q, [64:192]=0.1*phi_q
__device__ float g_Kext[NH * SQ * KE];        // [h][s][0:64]=k,        [64:192]=phi_k
__device__ float g_V   [NH * SQ * HD];
__device__ float g_Ctx [SQ * HID];
__device__ float g_Wsc [ (size_t)NH * SQ * SQ ]; // fallback weights buffer

// ---------------- tf32 helpers ----------------
__device__ __forceinline__ float tf32r(float x) {
    uint32_t u;
    asm("cvt.rna.tf32.f32 %0, %1;" : "=r"(u) : "f"(x));
    return __uint_as_float(u);
}

__device__ __forceinline__ void mma8(float c[4], const uint32_t a[4], const uint32_t b[2]) {
    asm volatile(
        "mma.sync.aligned.m16n8k8.row.col.f32.tf32.tf32.f32 "
        "{%0,%1,%2,%3},{%4,%5,%6,%7},{%8,%9},{%0,%1,%2,%3};\n"
        : "+f"(c[0]), "+f"(c[1]), "+f"(c[2]), "+f"(c[3])
        : "r"(a[0]), "r"(a[1]), "r"(a[2]), "r"(a[3]), "r"(b[0]), "r"(b[1]));
}

// stage ROWS x 32 fp32 tile (row-major, leading dim ld) into S[ROWS][LD] with tf32 rounding
template<int ROWS>
__device__ __forceinline__ void stageT(const float* __restrict__ g, int ld,
                                       float* __restrict__ S, int tid)
{
#pragma unroll
    for (int it = 0; it < ROWS / 32; it++) {
        int i = tid + (it << 8);
        int row = i >> 3;
        int c4 = (i & 7) << 2;
        float4 v = *(const float4*)(g + (size_t)row * ld + c4);
        v.x = tf32r(v.x); v.y = tf32r(v.y); v.z = tf32r(v.z); v.w = tf32r(v.w);
        *(float4*)(S + row * LD + c4) = v;
    }
}

// =======================================================================
// 128x128 ABt tensor-core engine: C[m][n] = sum_k A[m][k]*B[n][k]
// 256 threads = 8 warps (2x4), warp tile 64x32, mma m16n8k8 tf32.
// =======================================================================
__device__ __forceinline__ void tc_abt128(const float* __restrict__ A, int lda,
                                          const float* __restrict__ B, int ldb,
                                          int K, float* As, float* Bs,
                                          float acc[4][4][4])
{
    const int tid = threadIdx.x;
    const int w = tid >> 5, l = tid & 31;
    const int g = l >> 2, tg = l & 3;
    const int mB = (w >> 2) * 64, nB = (w & 3) * 32;
    const uint32_t* Au = (const uint32_t*)As;
    const uint32_t* Bu = (const uint32_t*)Bs;

    for (int k0 = 0; k0 < K; k0 += 32) {
        __syncthreads();
        stageT<128>(A + k0, lda, As, tid);
        stageT<128>(B + k0, ldb, Bs, tid);
        __syncthreads();
#pragma unroll
        for (int kk = 0; kk < 4; kk++) {
            uint32_t af[4][4], bf[4][2];
#pragma unroll
            for (int mi = 0; mi < 4; mi++) {
                int r = (mB + mi * 16 + g) * LD + kk * 8 + tg;
                af[mi][0] = Au[r];
                af[mi][1] = Au[r + 8 * LD];
                af[mi][2] = Au[r + 4];
                af[mi][3] = Au[r + 8 * LD + 4];
            }
#pragma unroll
            for (int ni = 0; ni < 4; ni++) {
                int r = (nB + ni * 8 + g) * LD + kk * 8 + tg;
                bf[ni][0] = Bu[r];
                bf[ni][1] = Bu[r + 4];
            }
#pragma unroll
            for (int mi = 0; mi < 4; mi++)
#pragma unroll
                for (int ni = 0; ni < 4; ni++)
                    mma8(acc[mi][ni], af[mi], bf[ni]);
        }
    }
}

// =======================================================================
// K1: QKV projections (tensor core). z = 0:Q 1:K 2:V. grid (6,16,3), 256 thr
// =======================================================================
__global__ __launch_bounds__(256) void k_qkv(const float* __restrict__ X,
    const float* __restrict__ Wq, const float* __restrict__ bq,
    const float* __restrict__ Wk, const float* __restrict__ bk,
    const float* __restrict__ Wv, const float* __restrict__ bv)
{
    __shared__ float As[128 * LD];
    __shared__ float Bs[128 * LD];
    const int z = blockIdx.z;
    const float* W    = (z == 0) ? Wq : (z == 1) ? Wk : Wv;
    const float* bias = (z == 0) ? bq : (z == 1) ? bk : bv;
    const int rowBase = blockIdx.y * 128;
    const int colBase = blockIdx.x * 128;

    float acc[4][4][4];
#pragma unroll
    for (int a = 0; a < 4; a++)
#pragma unroll
        for (int b = 0; b < 4; b++)
#pragma unroll
            for (int c = 0; c < 4; c++) acc[a][b][c] = 0.f;

    tc_abt128(X + (size_t)rowBase * HID, HID, W + (size_t)colBase * HID, HID,
              HID, As, Bs, acc);

    const int w = threadIdx.x >> 5, l = threadIdx.x & 31;
    const int g = l >> 2, tg = l & 3;
    const int mB = (w >> 2) * 64, nB = (w & 3) * 32;
#pragma unroll
    for (int mi = 0; mi < 4; mi++) {
#pragma unroll
        for (int ni = 0; ni < 4; ni++) {
#pragma unroll
            for (int cr = 0; cr < 4; cr++) {
                const int s = rowBase + mB + mi * 16 + g + ((cr >> 1) << 3);
                const int o = colBase + nB + ni * 8 + 2 * tg + (cr & 1);
                const float v = acc[mi][ni][cr] + bias[o];
                const int h = o >> 6, d = o & 63;
                if (z == 2)       g_V[((size_t)h * SQ + s) * HD + d] = v;
                else if (z == 1)  g_Kext[((size_t)h * SQ + s) * KE + d] = v;
                else              g_Qext[((size_t)h * SQ + s) * KE + d] = v;
            }
        }
    }
}

// =======================================================================
// K2: RFF features. grid (SQ/64=32, NH, 2: side 0=Q 1=K), 128 thr
// =======================================================================
__device__ __forceinline__ float blockReduceSum128(float v, volatile float* red)
{
    for (int o = 16; o > 0; o >>= 1) v += __shfl_xor_sync(0xffffffffu, v, o);
    const int w = threadIdx.x >> 5;
    if ((threadIdx.x & 31) == 0) red[w] = v;
    __syncthreads();
    return red[0] + red[1] + red[2] + red[3];
}

#define OMLD 129

__global__ __launch_bounds__(128) void k_phi(const float* __restrict__ omega,
                                             const float* __restrict__ rffb)
{
    __shared__ float omT[HD * OMLD];
    __shared__ float qrow[HD];
    __shared__ float redA[4];
    __shared__ float redB[4];

    const int tid  = threadIdx.x;
    const int h    = blockIdx.y;
    const int side = blockIdx.z;

    for (int i = tid; i < NF * HD; i += 128) {
        const int f = i >> 6, d = i & 63;
        omT[d * OMLD + f] = omega[((size_t)h * NF + f) * HD + d];
    }
    const float bf = rffb[h * NF + tid];
    float* ext = (side ? g_Kext : g_Qext) + (size_t)h * SQ * KE;
    const float segscale = side ? 1.0f : 0.1f;
    __syncthreads();

    for (int r = 0; r < 64; r++) {
        const int s = blockIdx.x * 64 + r;
        float* row = ext + (size_t)s * KE;
        __syncthreads();
        if (tid < 64) qrow[tid] = row[tid];
        __syncthreads();

        float p = (tid < 64) ? qrow[tid] * qrow[tid] : 0.f;
        const float ss  = blockReduceSum128(p, redA);
        const float inv = 1.0f / (sqrtf(ss) + 1e-5f);

        float dot = 0.f;
#pragma unroll 8
        for (int d = 0; d < HD; d++) dot += qrow[d] * omT[d * OMLD + tid];
        const float zv = inv * dot + bf;
        const float ph = 0.125f * cosf(zv);

        __syncthreads();
        const float pn2 = blockReduceSum128(ph * ph, redB);
        const float outv = ph / (sqrtf(pn2) + 1e-6f);

        row[HD + tid] = outv * segscale;
        if (side == 0 && tid < 64) row[tid] = qrow[tid] * 0.1125f;
    }
}

// =======================================================================
// K3: scores = Qext @ Kext^T + mask (tensor core). grid (16,16,12), 256 thr
// =======================================================================
__global__ __launch_bounds__(256) void k_scores(const float* __restrict__ mask,
                                                float* wts)
{
    __shared__ float As[128 * LD];
    __shared__ float Bs[128 * LD];
    float* W = wts ? wts : g_Wsc;
    const int h = blockIdx.z;
    const int rowBase = blockIdx.y * 128;
    const int colBase = blockIdx.x * 128;

    float acc[4][4][4];
#pragma unroll
    for (int a = 0; a < 4; a++)
#pragma unroll
        for (int b = 0; b < 4; b++)
#pragma unroll
            for (int c = 0; c < 4; c++) acc[a][b][c] = 0.f;

    const float* A = g_Qext + (size_t)h * SQ * KE + (size_t)rowBase * KE;
    const float* B = g_Kext + (size_t)h * SQ * KE + (size_t)colBase * KE;
    tc_abt128(A, KE, B, KE, KE, As, Bs, acc);

    float* Wh = W + (size_t)h * SQ * SQ;
    const int w = threadIdx.x >> 5, l = threadIdx.x & 31;
    const int g = l >> 2, tg = l & 3;
    const int mB = (w >> 2) * 64, nB = (w & 3) * 32;
#pragma unroll
    for (int mi = 0; mi < 4; mi++) {
#pragma unroll
        for (int ni = 0; ni < 4; ni++) {
            const int t0 = colBase + nB + ni * 8 + 2 * tg;
            const float mk0 = (mask[t0] - 1.0f) * 10000.0f;
            const float mk1 = (mask[t0 + 1] - 1.0f) * 10000.0f;
#pragma unroll
            for (int half = 0; half < 2; half++) {
                const int s = rowBase + mB + mi * 16 + g + half * 8;
                float2 v = make_float2(acc[mi][ni][half * 2 + 0] + mk0,
                                       acc[mi][ni][half * 2 + 1] + mk1);
                *(float2*)(Wh + (size_t)s * SQ + t0) = v;
            }
        }
    }
}

// =======================================================================
// K4: in-place row softmax over 2048 cols. grid (NH*SQ), 256 thr
// =======================================================================
__global__ __launch_bounds__(256) void k_softmax(float* wts)
{
    __shared__ float red[8];
    float* W = wts ? wts : g_Wsc;
    float4* p = (float4*)(W + (size_t)blockIdx.x * SQ);
    const int tid = threadIdx.x;

    float4 v0 = p[tid];
    float4 v1 = p[tid + 256];
    float m = fmaxf(fmaxf(fmaxf(v0.x, v0.y), fmaxf(v0.z, v0.w)),
                    fmaxf(fmaxf(v1.x, v1.y), fmaxf(v1.z, v1.w)));
    for (int o = 16; o > 0; o >>= 1) m = fmaxf(m, __shfl_xor_sync(0xffffffffu, m, o));
    if ((tid & 31) == 0) red[tid >> 5] = m;
    __syncthreads();
    m = red[0];
#pragma unroll
    for (int i = 1; i < 8; i++) m = fmaxf(m, red[i]);
    __syncthreads();

    v0.x = expf(v0.x - m); v0.y = expf(v0.y - m); v0.z = expf(v0.z - m); v0.w = expf(v0.w - m);
    v1.x = expf(v1.x - m); v1.y = expf(v1.y - m); v1.z = expf(v1.z - m); v1.w = expf(v1.w - m);
    float s = v0.x + v0.y + v0.z + v0.w + v1.x + v1.y + v1.z + v1.w;
    for (int o = 16; o > 0; o >>= 1) s += __shfl_xor_sync(0xffffffffu, s, o);
    if ((tid & 31) == 0) red[tid >> 5] = s;
    __syncthreads();
    s = red[0] + red[1] + red[2] + red[3] + red[4] + red[5] + red[6] + red[7];
    const float inv = 1.0f / s;

    v0.x *= inv; v0.y *= inv; v0.z *= inv; v0.w *= inv;
    v1.x *= inv; v1.y *= inv; v1.z *= inv; v1.w *= inv;
    p[tid] = v0;
    p[tid + 256] = v1;
}

// =======================================================================
// K5: context = weights @ V (tensor core). Block tile 64x64, 256 thr.
// A = weights [s][t] row-major (k=t), B = V [t][d] (already [k][n]).
// grid (1, 32, NH)
// =======================================================================
__global__ __launch_bounds__(256) void k_context(float* wts)
{
    __shared__ float As[64 * LD];      // [m][k]
    __shared__ float Bsv[32 * 72];     // [k][n], pad 72 -> conflict-free frag reads
    float* W = wts ? wts : g_Wsc;
    const int h = blockIdx.z;
    const int rowBase = blockIdx.y * 64;
    const float* A = W   + (size_t)h * SQ * SQ + (size_t)rowBase * SQ;
    const float* B = g_V + (size_t)h * SQ * HD;

    const int tid = threadIdx.x;
    const int w = tid >> 5, l = tid & 31;
    const int g = l >> 2, tg = l & 3;
    const int mB = (w >> 2) * 32, nB = (w & 3) * 16;
    const uint32_t* Au = (const uint32_t*)As;
    const uint32_t* Bu = (const uint32_t*)Bsv;

    float acc[2][2][4];
#pragma unroll
    for (int a = 0; a < 2; a++)
#pragma unroll
        for (int b = 0; b < 2; b++)
#pragma unroll
            for (int c = 0; c < 4; c++) acc[a][b][c] = 0.f;

    for (int k0 = 0; k0 < SQ; k0 += 32) {
        __syncthreads();
        stageT<64>(A + k0, SQ, As, tid);
        // V tile 32x64 direct copy [k][n]
#pragma unroll
        for (int it = 0; it < 2; it++) {
            int i = tid + (it << 8);
            int row = i >> 4;
            int c4 = (i & 15) << 2;
            float4 v = *(const float4*)(B + (size_t)(k0 + row) * HD + c4);
            v.x = tf32r(v.x); v.y = tf32r(v.y); v.z = tf32r(v.z); v.w = tf32r(v.w);
            *(float4*)(Bsv + row * 72 + c4) = v;
        }
        __syncthreads();
#pragma unroll
        for (int kk = 0; kk < 4; kk++) {
            uint32_t af[2][4], bf[2][2];
#pragma unroll
            for (int mi = 0; mi < 2; mi++) {
                int r = (mB + mi * 16 + g) * LD + kk * 8 + tg;
                af[mi][0] = Au[r];
                af[mi][1] = Au[r + 8 * LD];
                af[mi][2] = Au[r + 4];
                af[mi][3] = Au[r + 8 * LD + 4];
            }
#pragma unroll
            for (int ni = 0; ni < 2; ni++) {
                int r = (kk * 8 + tg) * 72 + nB + ni * 8 + g;
                bf[ni][0] = Bu[r];
                bf[ni][1] = Bu[r + 4 * 72];
            }
#pragma unroll
            for (int mi = 0; mi < 2; mi++)
#pragma unroll
                for (int ni = 0; ni < 2; ni++)
                    mma8(acc[mi][ni], af[mi], bf[ni]);
        }
    }

#pragma unroll
    for (int mi = 0; mi < 2; mi++) {
#pragma unroll
        for (int ni = 0; ni < 2; ni++) {
            const int d0 = nB + ni * 8 + 2 * tg;
#pragma unroll
            for (int half = 0; half < 2; half++) {
                const int s = rowBase + mB + mi * 16 + g + half * 8;
                float2 v = make_float2(acc[mi][ni][half * 2 + 0],
                                       acc[mi][ni][half * 2 + 1]);
                *(float2*)(g_Ctx + (size_t)s * HID + h * HD + d0) = v;
            }
        }
    }
}

// =======================================================================
// K6: output = Ctx @ Wo^T + bo (tensor core). grid (6, 16), 256 thr
// =======================================================================
__global__ __launch_bounds__(256) void k_outproj(const float* __restrict__ Wo,
                                                 const float* __restrict__ bo,
                                                 float* __restrict__ out)
{
    __shared__ float As[128 * LD];
    __shared__ float Bs[128 * LD];
    const int rowBase = blockIdx.y * 128;
    const int colBase = blockIdx.x * 128;

    float acc[4][4][4];
#pragma unroll
    for (int a = 0; a < 4; a++)
#pragma unroll
        for (int b = 0; b < 4; b++)
#pragma unroll
            for (int c = 0; c < 4; c++) acc[a][b][c] = 0.f;

    tc_abt128(g_Ctx + (size_t)rowBase * HID, HID,
              Wo + (size_t)colBase * HID, HID, HID, As, Bs, acc);

    const int w = threadIdx.x >> 5, l = threadIdx.x & 31;
    const int g = l >> 2, tg = l & 3;
    const int mB = (w >> 2) * 64, nB = (w & 3) * 32;
#pragma unroll
    for (int mi = 0; mi < 4; mi++) {
#pragma unroll
        for (int ni = 0; ni < 4; ni++) {
            const int o0 = colBase + nB + ni * 8 + 2 * tg;
            const float b0 = bo[o0], b1 = bo[o0 + 1];
#pragma unroll
            for (int half = 0; half < 2; half++) {
                const int s = rowBase + mB + mi * 16 + g + half * 8;
                float2 v = make_float2(acc[mi][ni][half * 2 + 0] + b0,
                                       acc[mi][ni][half * 2 + 1] + b1);
                *(float2*)(out + (size_t)s * HID + o0) = v;
            }
        }
    }
}

// =======================================================================
extern "C" void kernel_launch(void* const* d_in, const int* in_sizes, int n_in,
                              void* d_out, int out_size)
{
    const float* X    = (const float*)d_in[0];
    const float* mask = (const float*)d_in[1];
    const float* Wq   = (const float*)d_in[2];
    const float* bq   = (const float*)d_in[3];
    const float* Wk   = (const float*)d_in[4];
    const float* bk   = (const float*)d_in[5];
    const float* Wv   = (const float*)d_in[6];
    const float* bv   = (const float*)d_in[7];
    const float* Wo   = (const float*)d_in[8];
    const float* bo   = (const float*)d_in[9];
    const float* omega = (const float*)d_in[10];
    const float* rffb  = (const float*)d_in[11];

    float* out = (float*)d_out;
    float* wts = (out_size > SQ * HID) ? (out + (size_t)SQ * HID) : nullptr;

    k_qkv<<<dim3(HID / 128, SQ / 128, 3), 256>>>(X, Wq, bq, Wk, bk, Wv, bv);
    k_phi<<<dim3(SQ / 64, NH, 2), 128>>>(omega, rffb);
    k_scores<<<dim3(SQ / 128, SQ / 128, NH), 256>>>(mask, wts);
    k_softmax<<<dim3(NH * SQ), 256>>>(wts);
    k_context<<<dim3(1, SQ / 64, NH), 256>>>(wts);
    k_outproj<<<dim3(HID / 128, SQ / 128), 256>>>(Wo, bo, out);
}

// round 3
// speedup vs baseline: 2.1404x; 1.0494x over previous
#include <cuda_runtime.h>
#include <cuda_bf16.h>
#include <math.h>
#include <stdint.h>

#define SQ   2048
#define HID  768
#define NH   12
#define HD   64
#define NF   128
#define KE   192   // HD + NF extended contraction dim
#define LDH  40    // smem row pitch in halves (conflict-free frag reads)
#define LDU  20    // same pitch in u32

// ---------------- scratch (allocation-free: device globals) ----------------
__device__ float g_Qext[NH * SQ * KE];        // [h][s][0:64]=0.1125*q, [64:192]=0.1*phi_q
__device__ float g_Kext[NH * SQ * KE];        // [h][s][0:64]=k,        [64:192]=phi_k
__device__ float g_Vt  [NH * HD * SQ];        // [h][d][t]  (V transposed)
__device__ float g_Ctx [SQ * HID];
__device__ float g_Wsc [ (size_t)NH * SQ * SQ ]; // fallback weights buffer

// ---------------- bf16 split mma helpers ----------------
__device__ __forceinline__ void mma16(float c[4], const uint32_t a[4], const uint32_t b[2]) {
    asm volatile(
        "mma.sync.aligned.m16n8k16.row.col.f32.bf16.bf16.f32 "
        "{%0,%1,%2,%3},{%4,%5,%6,%7},{%8,%9},{%0,%1,%2,%3};\n"
        : "+f"(c[0]), "+f"(c[1]), "+f"(c[2]), "+f"(c[3])
        : "r"(a[0]), "r"(a[1]), "r"(a[2]), "r"(a[3]), "r"(b[0]), "r"(b[1]));
}

// convert a float4 into hi/lo bf16 pairs and store 4 halves each
__device__ __forceinline__ void cvtStore(float4 v, __nv_bfloat16* Sh, __nv_bfloat16* Sl,
                                         int row, int c4)
{
    __nv_bfloat162 h01 = __floats2bfloat162_rn(v.x, v.y);
    __nv_bfloat162 h23 = __floats2bfloat162_rn(v.z, v.w);
    float2 f01 = __bfloat1622float2(h01);
    float2 f23 = __bfloat1622float2(h23);
    __nv_bfloat162 l01 = __floats2bfloat162_rn(v.x - f01.x, v.y - f01.y);
    __nv_bfloat162 l23 = __floats2bfloat162_rn(v.z - f23.x, v.w - f23.y);
    *(__nv_bfloat162*)(Sh + row * LDH + c4)     = h01;
    *(__nv_bfloat162*)(Sh + row * LDH + c4 + 2) = h23;
    *(__nv_bfloat162*)(Sl + row * LDH + c4)     = l01;
    *(__nv_bfloat162*)(Sl + row * LDH + c4 + 2) = l23;
}

// load a ROWSx32 fp32 tile into registers (ROWS/32 float4 per thread)
template<int ROWS>
__device__ __forceinline__ void ldTile(const float* __restrict__ g, int ld,
                                       float4* v, int tid)
{
#pragma unroll
    for (int it = 0; it < ROWS / 32; it++) {
        int i = tid + (it << 8);
        int row = i >> 3;
        int c4 = (i & 7) << 2;
        v[it] = *(const float4*)(g + (size_t)row * ld + c4);
    }
}

template<int ROWS>
__device__ __forceinline__ void stTile(const float4* v, __nv_bfloat16* Sh,
                                       __nv_bfloat16* Sl, int tid)
{
#pragma unroll
    for (int it = 0; it < ROWS / 32; it++) {
        int i = tid + (it << 8);
        cvtStore(v[it], Sh, Sl, i >> 3, (i & 7) << 2);
    }
}

// perform the 2 k16 steps of one 32-k chunk: acc += Ah*Bh + Ah*Bl + Al*Bh
template<int MI, int NI>
__device__ __forceinline__ void mmaChunk(const uint32_t* AuH, const uint32_t* AuL,
                                         const uint32_t* BuH, const uint32_t* BuL,
                                         int mW, int nW, int g, int tg,
                                         float acc[MI][NI][4])
{
#pragma unroll
    for (int kk = 0; kk < 2; kk++) {
        uint32_t ah[MI][4], al[MI][4], bh[NI][2], bl[NI][2];
#pragma unroll
        for (int mi = 0; mi < MI; mi++) {
            int r = (mW + mi * 16 + g) * LDU + kk * 8 + tg;
            ah[mi][0] = AuH[r];            ah[mi][1] = AuH[r + 8 * LDU];
            ah[mi][2] = AuH[r + 4];        ah[mi][3] = AuH[r + 8 * LDU + 4];
            al[mi][0] = AuL[r];            al[mi][1] = AuL[r + 8 * LDU];
            al[mi][2] = AuL[r + 4];        al[mi][3] = AuL[r + 8 * LDU + 4];
        }
#pragma unroll
        for (int ni = 0; ni < NI; ni++) {
            int r = (nW + ni * 8 + g) * LDU + kk * 8 + tg;
            bh[ni][0] = BuH[r];  bh[ni][1] = BuH[r + 4];
            bl[ni][0] = BuL[r];  bl[ni][1] = BuL[r + 4];
        }
#pragma unroll
        for (int mi = 0; mi < MI; mi++)
#pragma unroll
            for (int ni = 0; ni < NI; ni++) {
                mma16(acc[mi][ni], ah[mi], bh[ni]);
                mma16(acc[mi][ni], ah[mi], bl[ni]);
                mma16(acc[mi][ni], al[mi], bh[ni]);
            }
    }
}

// =======================================================================
// 128x128 ABt engine (bf16-split): C[m][n] = sum_k A[m][k]*B[n][k]
// 256 thr = 8 warps (2x4), warp tile 64x32.
// =======================================================================
__device__ __forceinline__ void tc_abt128(const float* __restrict__ A, int lda,
                                          const float* __restrict__ B, int ldb,
                                          int K,
                                          __nv_bfloat16* Ah, __nv_bfloat16* Al,
                                          __nv_bfloat16* Bh, __nv_bfloat16* Bl,
                                          float acc[4][4][4])
{
    const int tid = threadIdx.x;
    const int w = tid >> 5, l = tid & 31;
    const int g = l >> 2, tg = l & 3;
    const int mW = (w >> 2) * 64, nW = (w & 3) * 32;
    const uint32_t* AuH = (const uint32_t*)Ah;
    const uint32_t* AuL = (const uint32_t*)Al;
    const uint32_t* BuH = (const uint32_t*)Bh;
    const uint32_t* BuL = (const uint32_t*)Bl;

    float4 va[4], vb[4];
    ldTile<128>(A, lda, va, tid);
    ldTile<128>(B, ldb, vb, tid);

    for (int k0 = 0; k0 < K; k0 += 32) {
        __syncthreads();
        stTile<128>(va, Ah, Al, tid);
        stTile<128>(vb, Bh, Bl, tid);
        __syncthreads();
        if (k0 + 32 < K) {
            ldTile<128>(A + k0 + 32, lda, va, tid);
            ldTile<128>(B + k0 + 32, ldb, vb, tid);
        }
        mmaChunk<4, 4>(AuH, AuL, BuH, BuL, mW, nW, g, tg, acc);
    }
}

// =======================================================================
// K1: QKV projections. z = 0:Q 1:K 2:V. grid (6,16,3), 256 thr
// =======================================================================
__global__ __launch_bounds__(256) void k_qkv(const float* __restrict__ X,
    const float* __restrict__ Wq, const float* __restrict__ bq,
    const float* __restrict__ Wk, const float* __restrict__ bk,
    const float* __restrict__ Wv, const float* __restrict__ bv)
{
    __shared__ __nv_bfloat16 Ah[128 * LDH], Al[128 * LDH];
    __shared__ __nv_bfloat16 Bh[128 * LDH], Bl[128 * LDH];
    const int z = blockIdx.z;
    const float* W    = (z == 0) ? Wq : (z == 1) ? Wk : Wv;
    const float* bias = (z == 0) ? bq : (z == 1) ? bk : bv;
    const int rowBase = blockIdx.y * 128;
    const int colBase = blockIdx.x * 128;

    float acc[4][4][4];
#pragma unroll
    for (int a = 0; a < 4; a++)
#pragma unroll
        for (int b = 0; b < 4; b++)
#pragma unroll
            for (int c = 0; c < 4; c++) acc[a][b][c] = 0.f;

    tc_abt128(X + (size_t)rowBase * HID, HID, W + (size_t)colBase * HID, HID,
              HID, Ah, Al, Bh, Bl, acc);

    const int w = threadIdx.x >> 5, l = threadIdx.x & 31;
    const int g = l >> 2, tg = l & 3;
    const int mW = (w >> 2) * 64, nW = (w & 3) * 32;
#pragma unroll
    for (int mi = 0; mi < 4; mi++) {
#pragma unroll
        for (int ni = 0; ni < 4; ni++) {
#pragma unroll
            for (int cr = 0; cr < 4; cr++) {
                const int s = rowBase + mW + mi * 16 + g + ((cr >> 1) << 3);
                const int o = colBase + nW + ni * 8 + 2 * tg + (cr & 1);
                const float v = acc[mi][ni][cr] + bias[o];
                const int h = o >> 6, d = o & 63;
                if (z == 2)       g_Vt[((size_t)h * HD + d) * SQ + s] = v;
                else if (z == 1)  g_Kext[((size_t)h * SQ + s) * KE + d] = v;
                else              g_Qext[((size_t)h * SQ + s) * KE + d] = v;
            }
        }
    }
}

// =======================================================================
// K2: RFF features. grid (SQ/64=32, NH, 2: side 0=Q 1=K), 128 thr
// =======================================================================
__device__ __forceinline__ float blockReduceSum128(float v, volatile float* red)
{
    for (int o = 16; o > 0; o >>= 1) v += __shfl_xor_sync(0xffffffffu, v, o);
    const int w = threadIdx.x >> 5;
    if ((threadIdx.x & 31) == 0) red[w] = v;
    __syncthreads();
    return red[0] + red[1] + red[2] + red[3];
}

#define OMLD 129

__global__ __launch_bounds__(128) void k_phi(const float* __restrict__ omega,
                                             const float* __restrict__ rffb)
{
    __shared__ float omT[HD * OMLD];
    __shared__ float qrow[HD];
    __shared__ float redA[4];
    __shared__ float redB[4];

    const int tid  = threadIdx.x;
    const int h    = blockIdx.y;
    const int side = blockIdx.z;

    for (int i = tid; i < NF * HD; i += 128) {
        const int f = i >> 6, d = i & 63;
        omT[d * OMLD + f] = omega[((size_t)h * NF + f) * HD + d];
    }
    const float bf = rffb[h * NF + tid];
    float* ext = (side ? g_Kext : g_Qext) + (size_t)h * SQ * KE;
    const float segscale = side ? 1.0f : 0.1f;
    __syncthreads();

    for (int r = 0; r < 64; r++) {
        const int s = blockIdx.x * 64 + r;
        float* row = ext + (size_t)s * KE;
        __syncthreads();
        if (tid < 64) qrow[tid] = row[tid];
        __syncthreads();

        float p = (tid < 64) ? qrow[tid] * qrow[tid] : 0.f;
        const float ss  = blockReduceSum128(p, redA);
        const float inv = 1.0f / (sqrtf(ss) + 1e-5f);

        float dot = 0.f;
#pragma unroll 8
        for (int d = 0; d < HD; d++) dot += qrow[d] * omT[d * OMLD + tid];
        const float zv = inv * dot + bf;
        const float ph = 0.125f * cosf(zv);

        __syncthreads();
        const float pn2 = blockReduceSum128(ph * ph, redB);
        const float outv = ph / (sqrtf(pn2) + 1e-6f);

        row[HD + tid] = outv * segscale;
        if (side == 0 && tid < 64) row[tid] = qrow[tid] * 0.1125f;
    }
}

// =======================================================================
// K3: scores = Qext @ Kext^T + mask. grid (16,16,12), 256 thr
// =======================================================================
__global__ __launch_bounds__(256) void k_scores(const float* __restrict__ mask,
                                                float* wts)
{
    __shared__ __nv_bfloat16 Ah[128 * LDH], Al[128 * LDH];
    __shared__ __nv_bfloat16 Bh[128 * LDH], Bl[128 * LDH];
    float* W = wts ? wts : g_Wsc;
    const int h = blockIdx.z;
    const int rowBase = blockIdx.y * 128;
    const int colBase = blockIdx.x * 128;

    float acc[4][4][4];
#pragma unroll
    for (int a = 0; a < 4; a++)
#pragma unroll
        for (int b = 0; b < 4; b++)
#pragma unroll
            for (int c = 0; c < 4; c++) acc[a][b][c] = 0.f;

    const float* A = g_Qext + (size_t)h * SQ * KE + (size_t)rowBase * KE;
    const float* B = g_Kext + (size_t)h * SQ * KE + (size_t)colBase * KE;
    tc_abt128(A, KE, B, KE, KE, Ah, Al, Bh, Bl, acc);

    float* Wh = W + (size_t)h * SQ * SQ;
    const int w = threadIdx.x >> 5, l = threadIdx.x & 31;
    const int g = l >> 2, tg = l & 3;
    const int mW = (w >> 2) * 64, nW = (w & 3) * 32;
#pragma unroll
    for (int mi = 0; mi < 4; mi++) {
#pragma unroll
        for (int ni = 0; ni < 4; ni++) {
            const int t0 = colBase + nW + ni * 8 + 2 * tg;
            const float mk0 = (mask[t0] - 1.0f) * 10000.0f;
            const float mk1 = (mask[t0 + 1] - 1.0f) * 10000.0f;
#pragma unroll
            for (int half = 0; half < 2; half++) {
                const int s = rowBase + mW + mi * 16 + g + half * 8;
                float2 v = make_float2(acc[mi][ni][half * 2 + 0] + mk0,
                                       acc[mi][ni][half * 2 + 1] + mk1);
                *(float2*)(Wh + (size_t)s * SQ + t0) = v;
            }
        }
    }
}

// =======================================================================
// K4: in-place row softmax over 2048 cols. grid (NH*SQ), 256 thr
// =======================================================================
__global__ __launch_bounds__(256) void k_softmax(float* wts)
{
    __shared__ float red[8];
    float* W = wts ? wts : g_Wsc;
    float4* p = (float4*)(W + (size_t)blockIdx.x * SQ);
    const int tid = threadIdx.x;

    float4 v0 = p[tid];
    float4 v1 = p[tid + 256];
    float m = fmaxf(fmaxf(fmaxf(v0.x, v0.y), fmaxf(v0.z, v0.w)),
                    fmaxf(fmaxf(v1.x, v1.y), fmaxf(v1.z, v1.w)));
    for (int o = 16; o > 0; o >>= 1) m = fmaxf(m, __shfl_xor_sync(0xffffffffu, m, o));
    if ((tid & 31) == 0) red[tid >> 5] = m;
    __syncthreads();
    m = red[0];
#pragma unroll
    for (int i = 1; i < 8; i++) m = fmaxf(m, red[i]);
    __syncthreads();

    v0.x = expf(v0.x - m); v0.y = expf(v0.y - m); v0.z = expf(v0.z - m); v0.w = expf(v0.w - m);
    v1.x = expf(v1.x - m); v1.y = expf(v1.y - m); v1.z = expf(v1.z - m); v1.w = expf(v1.w - m);
    float s = v0.x + v0.y + v0.z + v0.w + v1.x + v1.y + v1.z + v1.w;
    for (int o = 16; o > 0; o >>= 1) s += __shfl_xor_sync(0xffffffffu, s, o);
    if ((tid & 31) == 0) red[tid >> 5] = s;
    __syncthreads();
    s = red[0] + red[1] + red[2] + red[3] + red[4] + red[5] + red[6] + red[7];
    const float inv = 1.0f / s;

    v0.x *= inv; v0.y *= inv; v0.z *= inv; v0.w *= inv;
    v1.x *= inv; v1.y *= inv; v1.z *= inv; v1.w *= inv;
    p[tid] = v0;
    p[tid + 256] = v1;
}

// =======================================================================
// K5: context = weights @ V. Block tile 128x64, warp tile 32x32.
// A = weights [s][t] (lda=SQ), B = g_Vt [d][t] (ldb=SQ). grid (16, NH)
// =======================================================================
__global__ __launch_bounds__(256) void k_context(float* wts)
{
    __shared__ __nv_bfloat16 Ah[128 * LDH], Al[128 * LDH];
    __shared__ __nv_bfloat16 Bh[64 * LDH],  Bl[64 * LDH];
    float* W = wts ? wts : g_Wsc;
    const int h = blockIdx.y;
    const int rowBase = blockIdx.x * 128;
    const float* A = W    + (size_t)h * SQ * SQ + (size_t)rowBase * SQ;
    const float* B = g_Vt + (size_t)h * HD * SQ;

    const int tid = threadIdx.x;
    const int w = tid >> 5, l = tid & 31;
    const int g = l >> 2, tg = l & 3;
    const int mW = (w >> 1) * 32, nW = (w & 1) * 32;
    const uint32_t* AuH = (const uint32_t*)Ah;
    const uint32_t* AuL = (const uint32_t*)Al;
    const uint32_t* BuH = (const uint32_t*)Bh;
    const uint32_t* BuL = (const uint32_t*)Bl;

    float acc[2][4][4];
#pragma unroll
    for (int a = 0; a < 2; a++)
#pragma unroll
        for (int b = 0; b < 4; b++)
#pragma unroll
            for (int c = 0; c < 4; c++) acc[a][b][c] = 0.f;

    float4 va[4], vb[2];
    ldTile<128>(A, SQ, va, tid);
    ldTile<64>(B, SQ, vb, tid);

    for (int k0 = 0; k0 < SQ; k0 += 32) {
        __syncthreads();
        stTile<128>(va, Ah, Al, tid);
        stTile<64>(vb, Bh, Bl, tid);
        __syncthreads();
        if (k0 + 32 < SQ) {
            ldTile<128>(A + k0 + 32, SQ, va, tid);
            ldTile<64>(B + k0 + 32, SQ, vb, tid);
        }
        mmaChunk<2, 4>(AuH, AuL, BuH, BuL, mW, nW, g, tg, acc);
    }

#pragma unroll
    for (int mi = 0; mi < 2; mi++) {
#pragma unroll
        for (int ni = 0; ni < 4; ni++) {
            const int d0 = nW + ni * 8 + 2 * tg;
#pragma unroll
            for (int half = 0; half < 2; half++) {
                const int s = rowBase + mW + mi * 16 + g + half * 8;
                float2 v = make_float2(acc[mi][ni][half * 2 + 0],
                                       acc[mi][ni][half * 2 + 1]);
                *(float2*)(g_Ctx + (size_t)s * HID + h * HD + d0) = v;
            }
        }
    }
}

// =======================================================================
// K6: output = Ctx @ Wo^T + bo. grid (6, 16), 256 thr
// =======================================================================
__global__ __launch_bounds__(256) void k_outproj(const float* __restrict__ Wo,
                                                 const float* __restrict__ bo,
                                                 float* __restrict__ out)
{
    __shared__ __nv_bfloat16 Ah[128 * LDH], Al[128 * LDH];
    __shared__ __nv_bfloat16 Bh[128 * LDH], Bl[128 * LDH];
    const int rowBase = blockIdx.y * 128;
    const int colBase = blockIdx.x * 128;

    float acc[4][4][4];
#pragma unroll
    for (int a = 0; a < 4; a++)
#pragma unroll
        for (int b = 0; b < 4; b++)
#pragma unroll
            for (int c = 0; c < 4; c++) acc[a][b][c] = 0.f;

    tc_abt128(g_Ctx + (size_t)rowBase * HID, HID,
              Wo + (size_t)colBase * HID, HID, HID, Ah, Al, Bh, Bl, acc);

    const int w = threadIdx.x >> 5, l = threadIdx.x & 31;
    const int g = l >> 2, tg = l & 3;
    const int mW = (w >> 2) * 64, nW = (w & 3) * 32;
#pragma unroll
    for (int mi = 0; mi < 4; mi++) {
#pragma unroll
        for (int ni = 0; ni < 4; ni++) {
            const int o0 = colBase + nW + ni * 8 + 2 * tg;
            const float b0 = bo[o0], b1 = bo[o0 + 1];
#pragma unroll
            for (int half = 0; half < 2; half++) {
                const int s = rowBase + mW + mi * 16 + g + half * 8;
                float2 v = make_float2(acc[mi][ni][half * 2 + 0] + b0,
                                       acc[mi][ni][half * 2 + 1] + b1);
                *(float2*)(out + (size_t)s * HID + o0) = v;
            }
        }
    }
}

// =======================================================================
extern "C" void kernel_launch(void* const* d_in, const int* in_sizes, int n_in,
                              void* d_out, int out_size)
{
    const float* X    = (const float*)d_in[0];
    const float* mask = (const float*)d_in[1];
    const float* Wq   = (const float*)d_in[2];
    const float* bq   = (const float*)d_in[3];
    const float* Wk   = (const float*)d_in[4];
    const float* bk   = (const float*)d_in[5];
    const float* Wv   = (const float*)d_in[6];
    const float* bv   = (const float*)d_in[7];
    const float* Wo   = (const float*)d_in[8];
    const float* bo   = (const float*)d_in[9];
    const float* omega = (const float*)d_in[10];
    const float* rffb  = (const float*)d_in[11];

    float* out = (float*)d_out;
    float* wts = (out_size > SQ * HID) ? (out + (size_t)SQ * HID) : nullptr;

    k_qkv<<<dim3(HID / 128, SQ / 128, 3), 256>>>(X, Wq, bq, Wk, bk, Wv, bv);
    k_phi<<<dim3(SQ / 64, NH, 2), 128>>>(omega, rffb);
    k_scores<<<dim3(SQ / 128, SQ / 128, NH), 256>>>(mask, wts);
    k_softmax<<<dim3(NH * SQ), 256>>>(wts);
    k_context<<<dim3(SQ / 128, NH), 256>>>(wts);
    k_outproj<<<dim3(HID / 128, SQ / 128), 256>>>(Wo, bo, out);
}

// round 4
// speedup vs baseline: 2.2024x; 1.0290x over previous
#include <cuda_runtime.h>
#include <cuda_bf16.h>
#include <math.h>
#include <stdint.h>

#define SQ   2048
#define HID  768
#define NH   12
#define HD   64
#define NF   128
#define KE   192   // HD + NF extended contraction dim
#define LDH  40    // smem row pitch in halves (conflict-free frags, 16B-aligned rows)

// dynamic smem budgets
#define BUFA (128 * LDH)              // halves per buffer (A / big B)
#define BUFB (64 * LDH)               // halves per buffer (context B)
#define SMEM_BIG ((size_t)(4 * 2 * BUFA) * 2)                     // 81920 B
#define SMEM_CTX ((size_t)(2 * 2 * BUFA + 2 * 2 * BUFB) * 2)      // 61440 B

// ---------------- scratch (allocation-free: device globals) ----------------
__device__ float g_Qext[NH * SQ * KE];        // [h][s][0:64]=0.1125*q, [64:192]=0.1*phi_q
__device__ float g_Kext[NH * SQ * KE];        // [h][s][0:64]=k,        [64:192]=phi_k
__device__ float g_Vt  [NH * HD * SQ];        // [h][d][t]  (V transposed)
__device__ float g_Ctx [SQ * HID];
__device__ float g_Wsc [ (size_t)NH * SQ * SQ ]; // fallback weights buffer

// ---------------- low-level helpers ----------------
__device__ __forceinline__ uint32_t smem_u32(const void* p) {
    return (uint32_t)__cvta_generic_to_shared(p);
}
__device__ __forceinline__ void ldm4(uint32_t r[4], uint32_t addr) {
    asm volatile("ldmatrix.sync.aligned.m8n8.x4.shared.b16 {%0,%1,%2,%3}, [%4];"
                 : "=r"(r[0]), "=r"(r[1]), "=r"(r[2]), "=r"(r[3]) : "r"(addr));
}
__device__ __forceinline__ void mma16(float c[4], const uint32_t a[4], const uint32_t b[2]) {
    asm volatile(
        "mma.sync.aligned.m16n8k16.row.col.f32.bf16.bf16.f32 "
        "{%0,%1,%2,%3},{%4,%5,%6,%7},{%8,%9},{%0,%1,%2,%3};\n"
        : "+f"(c[0]), "+f"(c[1]), "+f"(c[2]), "+f"(c[3])
        : "r"(a[0]), "r"(a[1]), "r"(a[2]), "r"(a[3]), "r"(b[0]), "r"(b[1]));
}

// convert a float4 into hi/lo bf16 pairs and store
__device__ __forceinline__ void cvtStore(float4 v, __nv_bfloat16* Sh, __nv_bfloat16* Sl,
                                         int row, int c4)
{
    __nv_bfloat162 h01 = __floats2bfloat162_rn(v.x, v.y);
    __nv_bfloat162 h23 = __floats2bfloat162_rn(v.z, v.w);
    float2 f01 = __bfloat1622float2(h01);
    float2 f23 = __bfloat1622float2(h23);
    __nv_bfloat162 l01 = __floats2bfloat162_rn(v.x - f01.x, v.y - f01.y);
    __nv_bfloat162 l23 = __floats2bfloat162_rn(v.z - f23.x, v.w - f23.y);
    *(__nv_bfloat162*)(Sh + row * LDH + c4)     = h01;
    *(__nv_bfloat162*)(Sh + row * LDH + c4 + 2) = h23;
    *(__nv_bfloat162*)(Sl + row * LDH + c4)     = l01;
    *(__nv_bfloat162*)(Sl + row * LDH + c4 + 2) = l23;
}

template<int ROWS>
__device__ __forceinline__ void ldTile(const float* __restrict__ g, int ld,
                                       float4* v, int tid)
{
#pragma unroll
    for (int it = 0; it < ROWS / 32; it++) {
        int i = tid + (it << 8);
        int row = i >> 3;
        int c4 = (i & 7) << 2;
        v[it] = *(const float4*)(g + (size_t)row * ld + c4);
    }
}

template<int ROWS>
__device__ __forceinline__ void stTile(const float4* v, __nv_bfloat16* Sh,
                                       __nv_bfloat16* Sl, int tid)
{
#pragma unroll
    for (int it = 0; it < ROWS / 32; it++) {
        int i = tid + (it << 8);
        cvtStore(v[it], Sh, Sl, i >> 3, (i & 7) << 2);
    }
}

// =======================================================================
// 128x128 ABt engine (bf16-split, ldmatrix, double buffered)
// 256 thr = 8 warps (2x4), warp tile 64x32.
// =======================================================================
__device__ __forceinline__ void tc_abt128(const float* __restrict__ A, int lda,
                                          const float* __restrict__ B, int ldb,
                                          int K, float acc[4][4][4])
{
    extern __shared__ __nv_bfloat16 sm[];
    __nv_bfloat16* Ah = sm;
    __nv_bfloat16* Al = Ah + 2 * BUFA;
    __nv_bfloat16* Bh = Al + 2 * BUFA;
    __nv_bfloat16* Bl = Bh + 2 * BUFA;

    const int tid = threadIdx.x, w = tid >> 5, l = tid & 31;
    const int mW = (w >> 2) * 64, nW = (w & 3) * 32;
    const int aLane = (l & 15) * LDH + (l >> 4) * 8;
    const int bLane = (((l >> 4) << 3) + (l & 7)) * LDH + ((l >> 3) & 1) * 8;
    const uint32_t aH = smem_u32(Ah) + (uint32_t)(aLane + mW * LDH) * 2;
    const uint32_t aL = smem_u32(Al) + (uint32_t)(aLane + mW * LDH) * 2;
    const uint32_t bH = smem_u32(Bh) + (uint32_t)(bLane + nW * LDH) * 2;
    const uint32_t bL = smem_u32(Bl) + (uint32_t)(bLane + nW * LDH) * 2;

    float4 va[4], vb[4];
    ldTile<128>(A, lda, va, tid);
    ldTile<128>(B, ldb, vb, tid);
    stTile<128>(va, Ah, Al, tid);
    stTile<128>(vb, Bh, Bl, tid);

    const int nCh = K >> 5;
    for (int c = 0; c < nCh; c++) {
        __syncthreads();
        if (c + 1 < nCh) {
            ldTile<128>(A + (c + 1) * 32, lda, va, tid);
            ldTile<128>(B + (c + 1) * 32, ldb, vb, tid);
        }
        const uint32_t bo = (uint32_t)(c & 1) * (BUFA * 2);
#pragma unroll
        for (int kk = 0; kk < 2; kk++) {
            uint32_t ah[4][4], al_[4][4], bh_[2][4], bl_[2][4];
#pragma unroll
            for (int mi = 0; mi < 4; mi++) {
                ldm4(ah[mi],  aH + bo + (uint32_t)(mi * 16 * LDH + kk * 16) * 2);
                ldm4(al_[mi], aL + bo + (uint32_t)(mi * 16 * LDH + kk * 16) * 2);
            }
#pragma unroll
            for (int np = 0; np < 2; np++) {
                ldm4(bh_[np], bH + bo + (uint32_t)(np * 16 * LDH + kk * 16) * 2);
                ldm4(bl_[np], bL + bo + (uint32_t)(np * 16 * LDH + kk * 16) * 2);
            }
#pragma unroll
            for (int mi = 0; mi < 4; mi++)
#pragma unroll
                for (int ni = 0; ni < 4; ni++) {
                    const int np = ni >> 1, q = (ni & 1) * 2;
                    uint32_t bhf[2] = { bh_[np][q], bh_[np][q + 1] };
                    uint32_t blf[2] = { bl_[np][q], bl_[np][q + 1] };
                    mma16(acc[mi][ni], ah[mi], bhf);
                    mma16(acc[mi][ni], ah[mi], blf);
                    mma16(acc[mi][ni], al_[mi], bhf);
                }
        }
        if (c + 1 < nCh) {
            const int p = (c + 1) & 1;
            stTile<128>(va, Ah + p * BUFA, Al + p * BUFA, tid);
            stTile<128>(vb, Bh + p * BUFA, Bl + p * BUFA, tid);
        }
    }
}

// =======================================================================
// K1: QKV projections. z = 0:Q 1:K 2:V. grid (6,16,3), 256 thr
// =======================================================================
__global__ __launch_bounds__(256) void k_qkv(const float* __restrict__ X,
    const float* __restrict__ Wq, const float* __restrict__ bq,
    const float* __restrict__ Wk, const float* __restrict__ bk,
    const float* __restrict__ Wv, const float* __restrict__ bv)
{
    const int z = blockIdx.z;
    const float* W    = (z == 0) ? Wq : (z == 1) ? Wk : Wv;
    const float* bias = (z == 0) ? bq : (z == 1) ? bk : bv;
    const int rowBase = blockIdx.y * 128;
    const int colBase = blockIdx.x * 128;

    float acc[4][4][4];
#pragma unroll
    for (int a = 0; a < 4; a++)
#pragma unroll
        for (int b = 0; b < 4; b++)
#pragma unroll
            for (int c = 0; c < 4; c++) acc[a][b][c] = 0.f;

    tc_abt128(X + (size_t)rowBase * HID, HID, W + (size_t)colBase * HID, HID,
              HID, acc);

    const int w = threadIdx.x >> 5, l = threadIdx.x & 31;
    const int g = l >> 2, tg = l & 3;
    const int mW = (w >> 2) * 64, nW = (w & 3) * 32;
#pragma unroll
    for (int mi = 0; mi < 4; mi++) {
#pragma unroll
        for (int ni = 0; ni < 4; ni++) {
#pragma unroll
            for (int cr = 0; cr < 4; cr++) {
                const int s = rowBase + mW + mi * 16 + g + ((cr >> 1) << 3);
                const int o = colBase + nW + ni * 8 + 2 * tg + (cr & 1);
                const float v = acc[mi][ni][cr] + bias[o];
                const int h = o >> 6, d = o & 63;
                if (z == 2)       g_Vt[((size_t)h * HD + d) * SQ + s] = v;
                else if (z == 1)  g_Kext[((size_t)h * SQ + s) * KE + d] = v;
                else              g_Qext[((size_t)h * SQ + s) * KE + d] = v;
            }
        }
    }
}

// =======================================================================
// K2: RFF features. grid (SQ/64=32, NH, 2: side 0=Q 1=K), 128 thr
// =======================================================================
__device__ __forceinline__ float blockReduceSum128(float v, volatile float* red)
{
    for (int o = 16; o > 0; o >>= 1) v += __shfl_xor_sync(0xffffffffu, v, o);
    const int w = threadIdx.x >> 5;
    if ((threadIdx.x & 31) == 0) red[w] = v;
    __syncthreads();
    return red[0] + red[1] + red[2] + red[3];
}

#define OMLD 129

__global__ __launch_bounds__(128) void k_phi(const float* __restrict__ omega,
                                             const float* __restrict__ rffb)
{
    __shared__ float omT[HD * OMLD];
    __shared__ float qrow[HD];
    __shared__ float redA[4];
    __shared__ float redB[4];

    const int tid  = threadIdx.x;
    const int h    = blockIdx.y;
    const int side = blockIdx.z;

    for (int i = tid; i < NF * HD; i += 128) {
        const int f = i >> 6, d = i & 63;
        omT[d * OMLD + f] = omega[((size_t)h * NF + f) * HD + d];
    }
    const float bf = rffb[h * NF + tid];
    float* ext = (side ? g_Kext : g_Qext) + (size_t)h * SQ * KE;
    const float segscale = side ? 1.0f : 0.1f;
    __syncthreads();

    for (int r = 0; r < 64; r++) {
        const int s = blockIdx.x * 64 + r;
        float* row = ext + (size_t)s * KE;
        __syncthreads();
        if (tid < 64) qrow[tid] = row[tid];
        __syncthreads();

        float p = (tid < 64) ? qrow[tid] * qrow[tid] : 0.f;
        const float ss  = blockReduceSum128(p, redA);
        const float inv = 1.0f / (sqrtf(ss) + 1e-5f);

        float dot = 0.f;
#pragma unroll 8
        for (int d = 0; d < HD; d++) dot += qrow[d] * omT[d * OMLD + tid];
        const float zv = inv * dot + bf;
        const float ph = 0.125f * cosf(zv);

        __syncthreads();
        const float pn2 = blockReduceSum128(ph * ph, redB);
        const float outv = ph / (sqrtf(pn2) + 1e-6f);

        row[HD + tid] = outv * segscale;
        if (side == 0 && tid < 64) row[tid] = qrow[tid] * 0.1125f;
    }
}

// =======================================================================
// K3: scores = Qext @ Kext^T + mask. grid (16,16,12), 256 thr
// =======================================================================
__global__ __launch_bounds__(256) void k_scores(const float* __restrict__ mask,
                                                float* wts)
{
    float* W = wts ? wts : g_Wsc;
    const int h = blockIdx.z;
    const int rowBase = blockIdx.y * 128;
    const int colBase = blockIdx.x * 128;

    float acc[4][4][4];
#pragma unroll
    for (int a = 0; a < 4; a++)
#pragma unroll
        for (int b = 0; b < 4; b++)
#pragma unroll
            for (int c = 0; c < 4; c++) acc[a][b][c] = 0.f;

    const float* A = g_Qext + (size_t)h * SQ * KE + (size_t)rowBase * KE;
    const float* B = g_Kext + (size_t)h * SQ * KE + (size_t)colBase * KE;
    tc_abt128(A, KE, B, KE, KE, acc);

    float* Wh = W + (size_t)h * SQ * SQ;
    const int w = threadIdx.x >> 5, l = threadIdx.x & 31;
    const int g = l >> 2, tg = l & 3;
    const int mW = (w >> 2) * 64, nW = (w & 3) * 32;
#pragma unroll
    for (int mi = 0; mi < 4; mi++) {
#pragma unroll
        for (int ni = 0; ni < 4; ni++) {
            const int t0 = colBase + nW + ni * 8 + 2 * tg;
            const float mk0 = (mask[t0] - 1.0f) * 10000.0f;
            const float mk1 = (mask[t0 + 1] - 1.0f) * 10000.0f;
#pragma unroll
            for (int half = 0; half < 2; half++) {
                const int s = rowBase + mW + mi * 16 + g + half * 8;
                float2 v = make_float2(acc[mi][ni][half * 2 + 0] + mk0,
                                       acc[mi][ni][half * 2 + 1] + mk1);
                *(float2*)(Wh + (size_t)s * SQ + t0) = v;
            }
        }
    }
}

// =======================================================================
// K4: in-place row softmax over 2048 cols. grid (NH*SQ), 256 thr
// =======================================================================
__global__ __launch_bounds__(256) void k_softmax(float* wts)
{
    __shared__ float red[8];
    float* W = wts ? wts : g_Wsc;
    float4* p = (float4*)(W + (size_t)blockIdx.x * SQ);
    const int tid = threadIdx.x;

    float4 v0 = p[tid];
    float4 v1 = p[tid + 256];
    float m = fmaxf(fmaxf(fmaxf(v0.x, v0.y), fmaxf(v0.z, v0.w)),
                    fmaxf(fmaxf(v1.x, v1.y), fmaxf(v1.z, v1.w)));
    for (int o = 16; o > 0; o >>= 1) m = fmaxf(m, __shfl_xor_sync(0xffffffffu, m, o));
    if ((tid & 31) == 0) red[tid >> 5] = m;
    __syncthreads();
    m = red[0];
#pragma unroll
    for (int i = 1; i < 8; i++) m = fmaxf(m, red[i]);
    __syncthreads();

    v0.x = expf(v0.x - m); v0.y = expf(v0.y - m); v0.z = expf(v0.z - m); v0.w = expf(v0.w - m);
    v1.x = expf(v1.x - m); v1.y = expf(v1.y - m); v1.z = expf(v1.z - m); v1.w = expf(v1.w - m);
    float s = v0.x + v0.y + v0.z + v0.w + v1.x + v1.y + v1.z + v1.w;
    for (int o = 16; o > 0; o >>= 1) s += __shfl_xor_sync(0xffffffffu, s, o);
    if ((tid & 31) == 0) red[tid >> 5] = s;
    __syncthreads();
    s = red[0] + red[1] + red[2] + red[3] + red[4] + red[5] + red[6] + red[7];
    const float inv = 1.0f / s;

    v0.x *= inv; v0.y *= inv; v0.z *= inv; v0.w *= inv;
    v1.x *= inv; v1.y *= inv; v1.z *= inv; v1.w *= inv;
    p[tid] = v0;
    p[tid + 256] = v1;
}

// =======================================================================
// K5: context = weights @ V. Block tile 128x64, warp tile 32x32 (warps 4x2).
// A = weights [s][t] (lda=SQ), B = g_Vt [d][t] (ldb=SQ). grid (16, NH)
// =======================================================================
__global__ __launch_bounds__(256) void k_context(float* wts)
{
    extern __shared__ __nv_bfloat16 sm[];
    __nv_bfloat16* Ah = sm;
    __nv_bfloat16* Al = Ah + 2 * BUFA;
    __nv_bfloat16* Bh = Al + 2 * BUFA;
    __nv_bfloat16* Bl = Bh + 2 * BUFB;

    float* W = wts ? wts : g_Wsc;
    const int h = blockIdx.y;
    const int rowBase = blockIdx.x * 128;
    const float* A = W    + (size_t)h * SQ * SQ + (size_t)rowBase * SQ;
    const float* B = g_Vt + (size_t)h * HD * SQ;

    const int tid = threadIdx.x, w = tid >> 5, l = tid & 31;
    const int g = l >> 2, tg = l & 3;
    const int mW = (w >> 1) * 32, nW = (w & 1) * 32;
    const int aLane = (l & 15) * LDH + (l >> 4) * 8;
    const int bLane = (((l >> 4) << 3) + (l & 7)) * LDH + ((l >> 3) & 1) * 8;
    const uint32_t aH = smem_u32(Ah) + (uint32_t)(aLane + mW * LDH) * 2;
    const uint32_t aL = smem_u32(Al) + (uint32_t)(aLane + mW * LDH) * 2;
    const uint32_t bH = smem_u32(Bh) + (uint32_t)(bLane + nW * LDH) * 2;
    const uint32_t bL = smem_u32(Bl) + (uint32_t)(bLane + nW * LDH) * 2;

    float acc[2][4][4];
#pragma unroll
    for (int a = 0; a < 2; a++)
#pragma unroll
        for (int b = 0; b < 4; b++)
#pragma unroll
            for (int c = 0; c < 4; c++) acc[a][b][c] = 0.f;

    float4 va[4], vb[2];
    ldTile<128>(A, SQ, va, tid);
    ldTile<64>(B, SQ, vb, tid);
    stTile<128>(va, Ah, Al, tid);
    stTile<64>(vb, Bh, Bl, tid);

    const int nCh = SQ >> 5;
    for (int c = 0; c < nCh; c++) {
        __syncthreads();
        if (c + 1 < nCh) {
            ldTile<128>(A + (c + 1) * 32, SQ, va, tid);
            ldTile<64>(B + (c + 1) * 32, SQ, vb, tid);
        }
        const uint32_t boA = (uint32_t)(c & 1) * (BUFA * 2);
        const uint32_t boB = (uint32_t)(c & 1) * (BUFB * 2);
#pragma unroll
        for (int kk = 0; kk < 2; kk++) {
            uint32_t ah[2][4], al_[2][4], bh_[2][4], bl_[2][4];
#pragma unroll
            for (int mi = 0; mi < 2; mi++) {
                ldm4(ah[mi],  aH + boA + (uint32_t)(mi * 16 * LDH + kk * 16) * 2);
                ldm4(al_[mi], aL + boA + (uint32_t)(mi * 16 * LDH + kk * 16) * 2);
            }
#pragma unroll
            for (int np = 0; np < 2; np++) {
                ldm4(bh_[np], bH + boB + (uint32_t)(np * 16 * LDH + kk * 16) * 2);
                ldm4(bl_[np], bL + boB + (uint32_t)(np * 16 * LDH + kk * 16) * 2);
            }
#pragma unroll
            for (int mi = 0; mi < 2; mi++)
#pragma unroll
                for (int ni = 0; ni < 4; ni++) {
                    const int np = ni >> 1, q = (ni & 1) * 2;
                    uint32_t bhf[2] = { bh_[np][q], bh_[np][q + 1] };
                    uint32_t blf[2] = { bl_[np][q], bl_[np][q + 1] };
                    mma16(acc[mi][ni], ah[mi], bhf);
                    mma16(acc[mi][ni], ah[mi], blf);
                    mma16(acc[mi][ni], al_[mi], bhf);
                }
        }
        if (c + 1 < nCh) {
            const int p = (c + 1) & 1;
            stTile<128>(va, Ah + p * BUFA, Al + p * BUFA, tid);
            stTile<64>(vb, Bh + p * BUFB, Bl + p * BUFB, tid);
        }
    }

#pragma unroll
    for (int mi = 0; mi < 2; mi++) {
#pragma unroll
        for (int ni = 0; ni < 4; ni++) {
            const int d0 = nW + ni * 8 + 2 * tg;
#pragma unroll
            for (int half = 0; half < 2; half++) {
                const int s = rowBase + mW + mi * 16 + g + half * 8;
                float2 v = make_float2(acc[mi][ni][half * 2 + 0],
                                       acc[mi][ni][half * 2 + 1]);
                *(float2*)(g_Ctx + (size_t)s * HID + h * HD + d0) = v;
            }
        }
    }
}

// =======================================================================
// K6: output = Ctx @ Wo^T + bo. grid (6, 16), 256 thr
// =======================================================================
__global__ __launch_bounds__(256) void k_outproj(const float* __restrict__ Wo,
                                                 const float* __restrict__ bo,
                                                 float* __restrict__ out)
{
    const int rowBase = blockIdx.y * 128;
    const int colBase = blockIdx.x * 128;

    float acc[4][4][4];
#pragma unroll
    for (int a = 0; a < 4; a++)
#pragma unroll
        for (int b = 0; b < 4; b++)
#pragma unroll
            for (int c = 0; c < 4; c++) acc[a][b][c] = 0.f;

    tc_abt128(g_Ctx + (size_t)rowBase * HID, HID,
              Wo + (size_t)colBase * HID, HID, HID, acc);

    const int w = threadIdx.x >> 5, l = threadIdx.x & 31;
    const int g = l >> 2, tg = l & 3;
    const int mW = (w >> 2) * 64, nW = (w & 3) * 32;
#pragma unroll
    for (int mi = 0; mi < 4; mi++) {
#pragma unroll
        for (int ni = 0; ni < 4; ni++) {
            const int o0 = colBase + nW + ni * 8 + 2 * tg;
            const float b0 = bo[o0], b1 = bo[o0 + 1];
#pragma unroll
            for (int half = 0; half < 2; half++) {
                const int s = rowBase + mW + mi * 16 + g + half * 8;
                float2 v = make_float2(acc[mi][ni][half * 2 + 0] + b0,
                                       acc[mi][ni][half * 2 + 1] + b1);
                *(float2*)(out + (size_t)s * HID + o0) = v;
            }
        }
    }
}

// =======================================================================
extern "C" void kernel_launch(void* const* d_in, const int* in_sizes, int n_in,
                              void* d_out, int out_size)
{
    const float* X    = (const float*)d_in[0];
    const float* mask = (const float*)d_in[1];
    const float* Wq   = (const float*)d_in[2];
    const float* bq   = (const float*)d_in[3];
    const float* Wk   = (const float*)d_in[4];
    const float* bk   = (const float*)d_in[5];
    const float* Wv   = (const float*)d_in[6];
    const float* bv   = (const float*)d_in[7];
    const float* Wo   = (const float*)d_in[8];
    const float* bo   = (const float*)d_in[9];
    const float* omega = (const float*)d_in[10];
    const float* rffb  = (const float*)d_in[11];

    float* out = (float*)d_out;
    float* wts = (out_size > SQ * HID) ? (out + (size_t)SQ * HID) : nullptr;

    cudaFuncSetAttribute(k_qkv,     cudaFuncAttributeMaxDynamicSharedMemorySize, (int)SMEM_BIG);
    cudaFuncSetAttribute(k_scores,  cudaFuncAttributeMaxDynamicSharedMemorySize, (int)SMEM_BIG);
    cudaFuncSetAttribute(k_outproj, cudaFuncAttributeMaxDynamicSharedMemorySize, (int)SMEM_BIG);
    cudaFuncSetAttribute(k_context, cudaFuncAttributeMaxDynamicSharedMemorySize, (int)SMEM_CTX);

    k_qkv<<<dim3(HID / 128, SQ / 128, 3), 256, SMEM_BIG>>>(X, Wq, bq, Wk, bk, Wv, bv);
    k_phi<<<dim3(SQ / 64, NH, 2), 128>>>(omega, rffb);
    k_scores<<<dim3(SQ / 128, SQ / 128, NH), 256, SMEM_BIG>>>(mask, wts);
    k_softmax<<<dim3(NH * SQ), 256>>>(wts);
    k_context<<<dim3(SQ / 128, NH), 256, SMEM_CTX>>>(wts);
    k_outproj<<<dim3(HID / 128, SQ / 128), 256, SMEM_BIG>>>(Wo, bo, out);
}